// round 14
// baseline (speedup 1.0000x reference)
#include <cuda_runtime.h>
#include <cstdint>

#define SS   2048
#define BB   2
#define EE   1024
#define HH   16
#define DD   64
#define BH   (BB*HH)
#define TOK  (BB*SS)
#define NT   256
#define PAD  20          // smem row pitch in floats (80B: 16B-aligned, conflict-free)
#define STG  3           // cp.async pipeline stages

// ---------------- scratch ----------------
__device__ float g_Q[BH * SS * DD];              // [B*H, S, d]
__device__ float g_K[BH * SS * DD];
__device__ float g_Vt[BH * DD * SS];             // V transposed [B*H, d, S]
__device__ float g_P[(size_t)BH * SS * SS];      // attn scores/probs [B*H, S, S]
__device__ float g_WA[TOK * EE];                 // attn out token-major

// ---------------- mma helpers ----------------
__device__ __forceinline__ uint32_t cvt_tf32_u(float f) {
    uint32_t u;
    asm("cvt.rna.tf32.f32 %0, %1;" : "=r"(u) : "f"(f));
    return u;
}

__device__ __forceinline__ void mma_tf32(float c[4], const uint32_t a[4],
                                         uint32_t b0, uint32_t b1) {
    asm volatile("mma.sync.aligned.m16n8k8.row.col.f32.tf32.tf32.f32 "
                 "{%0,%1,%2,%3}, {%4,%5,%6,%7}, {%8,%9}, {%0,%1,%2,%3};"
                 : "+f"(c[0]), "+f"(c[1]), "+f"(c[2]), "+f"(c[3])
                 : "r"(a[0]), "r"(a[1]), "r"(a[2]), "r"(a[3]), "r"(b0), "r"(b1));
}

// ---------------- GEMM core (cp.async 3-stage) ----------------
// C[128 x NTILE] tile at (m0,n0) of A[M,K] @ B[N,K]^T; both row-major; K % 16 == 0.
// 256 threads: 8 warps as 2(m) x 4(n); warp tile 64 x (NTILE/4).
template<int NTILE>
__device__ __forceinline__ void gemm_mma(const float* __restrict__ A, int lda,
                                         const float* __restrict__ B, int ldb,
                                         int m0, int n0, int K,
                                         float acc[4][NTILE/32][4]) {
    constexpr int WN  = NTILE / 4;
    constexpr int NTN = WN / 8;
    extern __shared__ float smb[];
    float* As = smb;                               // [STG][128][PAD]
    float* Bs = smb + STG * 128 * PAD;             // [STG][NTILE][PAD]

    int tid = threadIdx.x, wid = tid >> 5, lane = tid & 31;
    int gid = lane >> 2, tig = lane & 3;
    int wm = (wid & 1) * 64, wn = (wid >> 1) * WN;
    int nIter = K >> 4;

    auto issue = [&](int it) {
        if (it < nIter) {
            int kt = it << 4;
            int buf = it % STG;
            #pragma unroll
            for (int j = 0; j < 2; j++) {
                int slot = tid + j * 256;
                int r = slot >> 2, c4 = (slot & 3) << 2;
                uint32_t dst = (uint32_t)__cvta_generic_to_shared(
                    &As[(buf * 128 + r) * PAD + c4]);
                const float* src = A + (size_t)(m0 + r) * lda + kt + c4;
                asm volatile("cp.async.cg.shared.global [%0], [%1], 16;"
                             :: "r"(dst), "l"(src));
            }
            #pragma unroll
            for (int j = 0; j < NTILE / 64; j++) {
                int slot = tid + j * 256;
                int r = slot >> 2, c4 = (slot & 3) << 2;
                uint32_t dst = (uint32_t)__cvta_generic_to_shared(
                    &Bs[(buf * NTILE + r) * PAD + c4]);
                const float* src = B + (size_t)(n0 + r) * ldb + kt + c4;
                asm volatile("cp.async.cg.shared.global [%0], [%1], 16;"
                             :: "r"(dst), "l"(src));
            }
        }
        asm volatile("cp.async.commit_group;" ::: "memory");
    };

    issue(0); issue(1);
    for (int it = 0; it < nIter; it++) {
        asm volatile("cp.async.wait_group 1;" ::: "memory");
        __syncthreads();
        issue(it + 2);
        const float* Ab = As + (it % STG) * 128 * PAD;
        const float* Bb = Bs + (it % STG) * NTILE * PAD;
        #pragma unroll
        for (int kk = 0; kk < 16; kk += 8) {
            uint32_t af[4][4];
            #pragma unroll
            for (int mt = 0; mt < 4; mt++) {
                af[mt][0] = cvt_tf32_u(Ab[(wm + mt * 16 + gid    ) * PAD + kk + tig]);
                af[mt][1] = cvt_tf32_u(Ab[(wm + mt * 16 + gid + 8) * PAD + kk + tig]);
                af[mt][2] = cvt_tf32_u(Ab[(wm + mt * 16 + gid    ) * PAD + kk + tig + 4]);
                af[mt][3] = cvt_tf32_u(Ab[(wm + mt * 16 + gid + 8) * PAD + kk + tig + 4]);
            }
            #pragma unroll
            for (int nt = 0; nt < NTN; nt++) {
                uint32_t b0 = cvt_tf32_u(Bb[(wn + nt * 8 + gid) * PAD + kk + tig]);
                uint32_t b1 = cvt_tf32_u(Bb[(wn + nt * 8 + gid) * PAD + kk + tig + 4]);
                #pragma unroll
                for (int mt = 0; mt < 4; mt++)
                    mma_tf32(acc[mt][nt], af[mt], b0, b1);
            }
        }
        __syncthreads();
    }
}

#define EPI_SETUP() \
    int tid = threadIdx.x, wid = tid >> 5, lane = tid & 31; \
    int gid = lane >> 2, tig = lane & 3; \
    int wm = (wid & 1) * 64; (void)wm; \
    int wn = (wid >> 1) * WN; (void)wn; (void)tid;

// ---------------- kernel 1: QKV projection (reads x [S,B,E] directly) ----------------
__global__ void k_qkv(const float* __restrict__ x,
                      const float* __restrict__ qkv_w, const float* __restrict__ qkv_b) {
    constexpr int WN = 32;
    int m0 = blockIdx.y * 128, n0 = blockIdx.x * 128;
    int bb = m0 >> 11;
    float acc[4][4][4] = {};
    gemm_mma<128>(x + (size_t)bb * EE, BB * EE, qkv_w, EE, m0 & (SS - 1), n0, EE, acc);
    EPI_SETUP();
    int which = n0 >> 10;
    #pragma unroll
    for (int mt = 0; mt < 4; mt++) {
        #pragma unroll
        for (int nt = 0; nt < 4; nt++) {
            int col = n0 + wn + nt * 8 + 2 * tig;
            int inner = col & 1023, h = inner >> 6, dd = inner & 63;
            float b0 = qkv_b[col], b1 = qkv_b[col + 1];
            #pragma unroll
            for (int half = 0; half < 2; half++) {
                int row = m0 + wm + mt * 16 + gid + half * 8;
                int b = row >> 11, s = row & (SS - 1);
                float v0 = acc[mt][nt][half * 2] + b0;
                float v1 = acc[mt][nt][half * 2 + 1] + b1;
                if (which == 2) {
                    size_t base = (size_t)(b * HH + h) * DD;
                    g_Vt[(base + dd)     * SS + s] = v0;
                    g_Vt[(base + dd + 1) * SS + s] = v1;
                } else {
                    float* dst = which ? g_K : g_Q;
                    *(float2*)&dst[((size_t)(b * HH + h) * SS + s) * DD + dd] =
                        make_float2(v0, v1);
                }
            }
        }
    }
}

// ---------------- kernel 2: scores = QK^T/8 + masks -> g_P ----------------
__global__ void k_scores(const float* __restrict__ attn_mask,
                         const unsigned char* __restrict__ kpm) {
    constexpr int WN = 32;
    int bh = blockIdx.z, b = bh >> 4;
    int m0 = blockIdx.y * 128, n0 = blockIdx.x * 128;
    const float* Aq = g_Q + (size_t)bh * SS * DD;
    const float* Bk = g_K + (size_t)bh * SS * DD;
    float acc[4][4][4] = {};
    gemm_mma<128>(Aq, DD, Bk, DD, m0, n0, DD, acc);
    EPI_SETUP();
    float* pbase = g_P + (size_t)bh * SS * SS;
    #pragma unroll
    for (int mt = 0; mt < 4; mt++) {
        #pragma unroll
        for (int nt = 0; nt < 4; nt++) {
            int k = n0 + wn + nt * 8 + 2 * tig;
            float p0 = kpm[b * SS + k]     ? -1e30f : 0.0f;
            float p1 = kpm[b * SS + k + 1] ? -1e30f : 0.0f;
            #pragma unroll
            for (int half = 0; half < 2; half++) {
                int q = m0 + wm + mt * 16 + gid + half * 8;
                const float* am = attn_mask + (size_t)q * SS + k;
                float2 v = make_float2(acc[mt][nt][half * 2]     * 0.125f + am[0] + p0,
                                       acc[mt][nt][half * 2 + 1] * 0.125f + am[1] + p1);
                *(float2*)&pbase[(size_t)q * SS + k] = v;
            }
        }
    }
}

// ---------------- kernel 3: streaming softmax (in place) + attn_mean ----------------
__global__ void k_softmax(float* __restrict__ out_am) {
    int bq = blockIdx.x;
    int b = bq >> 11, q = bq & (SS - 1);
    int tid = threadIdx.x, wid = tid >> 5, lane = tid & 31;
    __shared__ float red[8];
    __shared__ float bc;
    float accv[8] = {};
    float* pbase = g_P + ((size_t)(b * HH) * SS + q) * SS;
    const size_t hstr = (size_t)SS * SS;
    const int c0 = tid * 8;

    for (int h = 0; h < HH; h++) {
        float* gr = pbase + h * hstr;
        float4 v0 = *(float4*)(gr + c0);
        float4 v1 = *(float4*)(gr + c0 + 4);
        float v[8] = {v0.x, v0.y, v0.z, v0.w, v1.x, v1.y, v1.z, v1.w};

        float mx = v[0];
        #pragma unroll
        for (int j = 1; j < 8; j++) mx = fmaxf(mx, v[j]);
        #pragma unroll
        for (int st = 16; st > 0; st >>= 1)
            mx = fmaxf(mx, __shfl_xor_sync(0xFFFFFFFF, mx, st));
        if (lane == 0) red[wid] = mx;
        __syncthreads();
        if (tid == 0) {
            float m = red[0];
            #pragma unroll
            for (int i = 1; i < 8; i++) m = fmaxf(m, red[i]);
            bc = m;
        }
        __syncthreads();
        mx = bc;

        float sum = 0.f;
        #pragma unroll
        for (int j = 0; j < 8; j++) { v[j] = __expf(v[j] - mx); sum += v[j]; }
        #pragma unroll
        for (int st = 16; st > 0; st >>= 1)
            sum += __shfl_xor_sync(0xFFFFFFFF, sum, st);
        __syncthreads();
        if (lane == 0) red[wid] = sum;
        __syncthreads();
        if (tid == 0) {
            float s = 0.f;
            #pragma unroll
            for (int i = 0; i < 8; i++) s += red[i];
            bc = s;
        }
        __syncthreads();
        float inv = 1.0f / bc;

        #pragma unroll
        for (int j = 0; j < 8; j++) { v[j] *= inv; accv[j] += v[j]; }
        *(float4*)(gr + c0)     = make_float4(v[0], v[1], v[2], v[3]);
        *(float4*)(gr + c0 + 4) = make_float4(v[4], v[5], v[6], v[7]);
        __syncthreads();
    }

    float* am = out_am + (size_t)bq * SS;
    *(float4*)(am + c0)     = make_float4(accv[0] * (1.0f / HH), accv[1] * (1.0f / HH),
                                          accv[2] * (1.0f / HH), accv[3] * (1.0f / HH));
    *(float4*)(am + c0 + 4) = make_float4(accv[4] * (1.0f / HH), accv[5] * (1.0f / HH),
                                          accv[6] * (1.0f / HH), accv[7] * (1.0f / HH));
}

// ---------------- kernel 4: O = P @ Vt^T ----------------
__global__ void k_pv() {
    constexpr int WN = 16;
    int bh = blockIdx.y, b = bh >> 4, h = bh & 15;
    int m0 = blockIdx.x * 128;
    const float* A  = g_P  + (size_t)bh * SS * SS;
    const float* Bv = g_Vt + (size_t)bh * DD * SS;   // [d][s] row-major = B[N][K]
    float acc[4][2][4] = {};
    gemm_mma<64>(A, SS, Bv, SS, m0, 0, SS, acc);
    EPI_SETUP();
    #pragma unroll
    for (int mt = 0; mt < 4; mt++) {
        #pragma unroll
        for (int nt = 0; nt < 2; nt++) {
            int dd = wn + nt * 8 + 2 * tig;
            #pragma unroll
            for (int half = 0; half < 2; half++) {
                int q = m0 + wm + mt * 16 + gid + half * 8;
                float2 v = make_float2(acc[mt][nt][half * 2], acc[mt][nt][half * 2 + 1]);
                *(float2*)&g_WA[(size_t)(b * SS + q) * EE + h * DD + dd] = v;
            }
        }
    }
}

// ---------------- kernel 5: out = WA @ out_w^T + out_b -> [S,B,E] ----------------
__global__ void k_out(const float* __restrict__ out_w, const float* __restrict__ out_b,
                      float* __restrict__ dout) {
    constexpr int WN = 32;
    int m0 = blockIdx.y * 128, n0 = blockIdx.x * 128;
    float acc[4][4][4] = {};
    gemm_mma<128>(g_WA, EE, out_w, EE, m0, n0, EE, acc);
    EPI_SETUP();
    #pragma unroll
    for (int mt = 0; mt < 4; mt++) {
        #pragma unroll
        for (int nt = 0; nt < 4; nt++) {
            int col = n0 + wn + nt * 8 + 2 * tig;
            float b0 = out_b[col], b1 = out_b[col + 1];
            #pragma unroll
            for (int half = 0; half < 2; half++) {
                int row = m0 + wm + mt * 16 + gid + half * 8;
                int b = row >> 11, s = row & (SS - 1);
                float2 v = make_float2(acc[mt][nt][half * 2] + b0,
                                       acc[mt][nt][half * 2 + 1] + b1);
                *(float2*)&dout[((size_t)s * BB + b) * EE + col] = v;
            }
        }
    }
}

// ---------------- launch ----------------
extern "C" void kernel_launch(void* const* d_in, const int* in_sizes, int n_in,
                              void* d_out, int out_size) {
    const float*         x         = (const float*)d_in[0];
    const float*         attn_mask = (const float*)d_in[1];
    const unsigned char* kpm       = (const unsigned char*)d_in[2];
    const float*         qkv_w     = (const float*)d_in[3];
    const float*         qkv_b     = (const float*)d_in[4];
    const float*         out_w     = (const float*)d_in[5];
    const float*         out_b     = (const float*)d_in[6];

    float* out    = (float*)d_out;
    float* out_am = out + (size_t)SS * BB * EE;

    const int smem128 = STG * (128 + 128) * PAD * 4;   // 61440
    const int smem64  = STG * (128 + 64)  * PAD * 4;   // 46080
    cudaFuncSetAttribute(k_qkv,    cudaFuncAttributeMaxDynamicSharedMemorySize, smem128);
    cudaFuncSetAttribute(k_scores, cudaFuncAttributeMaxDynamicSharedMemorySize, smem128);
    cudaFuncSetAttribute(k_out,    cudaFuncAttributeMaxDynamicSharedMemorySize, smem128);
    cudaFuncSetAttribute(k_pv,     cudaFuncAttributeMaxDynamicSharedMemorySize, smem64);

    k_qkv<<<dim3(3 * EE / 128, TOK / 128), NT, smem128>>>(x, qkv_w, qkv_b);
    k_scores<<<dim3(SS / 128, SS / 128, BH), NT, smem128>>>(attn_mask, kpm);
    k_softmax<<<BB * SS, 256>>>(out_am);
    k_pv<<<dim3(SS / 128, BH), NT, smem64>>>();
    k_out<<<dim3(EE / 128, TOK / 128), NT, smem128>>>(out_w, out_b, out);
}

// round 15
// speedup vs baseline: 1.5284x; 1.5284x over previous
#include <cuda_runtime.h>
#include <cstdint>

#define SS   2048
#define BB   2
#define EE   1024
#define HH   16
#define DD   64
#define BH   (BB*HH)
#define TOK  (BB*SS)
#define NT   256
#define PAD  20          // smem row pitch in floats (80B: 16B-aligned, conflict-free)
#define STG  3           // cp.async pipeline stages

// ---------------- scratch ----------------
__device__ float g_Q[BH * SS * DD];              // [B*H, S, d]
__device__ float g_K[BH * SS * DD];
__device__ float g_Vt[BH * DD * SS];             // V transposed [B*H, d, S]
__device__ float g_P[(size_t)BH * SS * SS];      // attn scores/probs [B*H, S, S]
__device__ float g_WA[TOK * EE];                 // attn out token-major

// ---------------- mma helpers ----------------
__device__ __forceinline__ uint32_t cvt_tf32_u(float f) {
    uint32_t u;
    asm("cvt.rna.tf32.f32 %0, %1;" : "=r"(u) : "f"(f));
    return u;
}

__device__ __forceinline__ void mma_tf32(float c[4], const uint32_t a[4],
                                         uint32_t b0, uint32_t b1) {
    asm volatile("mma.sync.aligned.m16n8k8.row.col.f32.tf32.tf32.f32 "
                 "{%0,%1,%2,%3}, {%4,%5,%6,%7}, {%8,%9}, {%0,%1,%2,%3};"
                 : "+f"(c[0]), "+f"(c[1]), "+f"(c[2]), "+f"(c[3])
                 : "r"(a[0]), "r"(a[1]), "r"(a[2]), "r"(a[3]), "r"(b0), "r"(b1));
}

// ---------------- GEMM core (cp.async 3-stage) ----------------
// C[128 x NTILE] tile at (m0,n0) of A[M,K] @ B[N,K]^T; both row-major; K % 16 == 0.
// 256 threads: 8 warps as 2(m) x 4(n); warp tile 64 x (NTILE/4).
template<int NTILE>
__device__ __forceinline__ void gemm_mma(const float* __restrict__ A, int lda,
                                         const float* __restrict__ B, int ldb,
                                         int m0, int n0, int K,
                                         float acc[4][NTILE/32][4]) {
    constexpr int WN  = NTILE / 4;
    constexpr int NTN = WN / 8;
    extern __shared__ float smb[];
    float* As = smb;                               // [STG][128][PAD]
    float* Bs = smb + STG * 128 * PAD;             // [STG][NTILE][PAD]

    int tid = threadIdx.x, wid = tid >> 5, lane = tid & 31;
    int gid = lane >> 2, tig = lane & 3;
    int wm = (wid & 1) * 64, wn = (wid >> 1) * WN;
    int nIter = K >> 4;

    auto issue = [&](int it) {
        if (it < nIter) {
            int kt = it << 4;
            int buf = it % STG;
            #pragma unroll
            for (int j = 0; j < 2; j++) {
                int slot = tid + j * 256;
                int r = slot >> 2, c4 = (slot & 3) << 2;
                uint32_t dst = (uint32_t)__cvta_generic_to_shared(
                    &As[(buf * 128 + r) * PAD + c4]);
                const float* src = A + (size_t)(m0 + r) * lda + kt + c4;
                asm volatile("cp.async.cg.shared.global [%0], [%1], 16;"
                             :: "r"(dst), "l"(src));
            }
            #pragma unroll
            for (int j = 0; j < NTILE / 64; j++) {
                int slot = tid + j * 256;
                int r = slot >> 2, c4 = (slot & 3) << 2;
                uint32_t dst = (uint32_t)__cvta_generic_to_shared(
                    &Bs[(buf * NTILE + r) * PAD + c4]);
                const float* src = B + (size_t)(n0 + r) * ldb + kt + c4;
                asm volatile("cp.async.cg.shared.global [%0], [%1], 16;"
                             :: "r"(dst), "l"(src));
            }
        }
        asm volatile("cp.async.commit_group;" ::: "memory");
    };

    issue(0); issue(1);
    for (int it = 0; it < nIter; it++) {
        asm volatile("cp.async.wait_group 1;" ::: "memory");
        __syncthreads();
        issue(it + 2);
        const float* Ab = As + (it % STG) * 128 * PAD;
        const float* Bb = Bs + (it % STG) * NTILE * PAD;
        #pragma unroll
        for (int kk = 0; kk < 16; kk += 8) {
            uint32_t af[4][4];
            #pragma unroll
            for (int mt = 0; mt < 4; mt++) {
                af[mt][0] = cvt_tf32_u(Ab[(wm + mt * 16 + gid    ) * PAD + kk + tig]);
                af[mt][1] = cvt_tf32_u(Ab[(wm + mt * 16 + gid + 8) * PAD + kk + tig]);
                af[mt][2] = cvt_tf32_u(Ab[(wm + mt * 16 + gid    ) * PAD + kk + tig + 4]);
                af[mt][3] = cvt_tf32_u(Ab[(wm + mt * 16 + gid + 8) * PAD + kk + tig + 4]);
            }
            #pragma unroll
            for (int nt = 0; nt < NTN; nt++) {
                uint32_t b0 = cvt_tf32_u(Bb[(wn + nt * 8 + gid) * PAD + kk + tig]);
                uint32_t b1 = cvt_tf32_u(Bb[(wn + nt * 8 + gid) * PAD + kk + tig + 4]);
                #pragma unroll
                for (int mt = 0; mt < 4; mt++)
                    mma_tf32(acc[mt][nt], af[mt], b0, b1);
            }
        }
        __syncthreads();
    }
}

#define EPI_SETUP() \
    int tid = threadIdx.x, wid = tid >> 5, lane = tid & 31; \
    int gid = lane >> 2, tig = lane & 3; \
    int wm = (wid & 1) * 64; (void)wm; \
    int wn = (wid >> 1) * WN; (void)wn; (void)tid;

// ---------------- kernel 1: QKV projection (reads x [S,B,E] directly) ----------------
__global__ void k_qkv(const float* __restrict__ x,
                      const float* __restrict__ qkv_w, const float* __restrict__ qkv_b) {
    constexpr int WN = 32;
    int m0 = blockIdx.y * 128, n0 = blockIdx.x * 128;
    int bb = m0 >> 11;
    float acc[4][4][4] = {};
    gemm_mma<128>(x + (size_t)bb * EE, BB * EE, qkv_w, EE, m0 & (SS - 1), n0, EE, acc);
    EPI_SETUP();
    int which = n0 >> 10;
    #pragma unroll
    for (int mt = 0; mt < 4; mt++) {
        #pragma unroll
        for (int nt = 0; nt < 4; nt++) {
            int col = n0 + wn + nt * 8 + 2 * tig;
            int inner = col & 1023, h = inner >> 6, dd = inner & 63;
            float b0 = qkv_b[col], b1 = qkv_b[col + 1];
            #pragma unroll
            for (int half = 0; half < 2; half++) {
                int row = m0 + wm + mt * 16 + gid + half * 8;
                int b = row >> 11, s = row & (SS - 1);
                float v0 = acc[mt][nt][half * 2] + b0;
                float v1 = acc[mt][nt][half * 2 + 1] + b1;
                if (which == 2) {
                    size_t base = (size_t)(b * HH + h) * DD;
                    g_Vt[(base + dd)     * SS + s] = v0;
                    g_Vt[(base + dd + 1) * SS + s] = v1;
                } else {
                    float* dst = which ? g_K : g_Q;
                    *(float2*)&dst[((size_t)(b * HH + h) * SS + s) * DD + dd] =
                        make_float2(v0, v1);
                }
            }
        }
    }
}

// ---------------- kernel 2: scores = QK^T/8 + masks -> g_P ----------------
__global__ void k_scores(const float* __restrict__ attn_mask,
                         const unsigned char* __restrict__ kpm) {
    constexpr int WN = 32;
    int bh = blockIdx.z, b = bh >> 4;
    int m0 = blockIdx.y * 128, n0 = blockIdx.x * 128;
    const float* Aq = g_Q + (size_t)bh * SS * DD;
    const float* Bk = g_K + (size_t)bh * SS * DD;
    float acc[4][4][4] = {};
    gemm_mma<128>(Aq, DD, Bk, DD, m0, n0, DD, acc);
    EPI_SETUP();
    float* pbase = g_P + (size_t)bh * SS * SS;
    #pragma unroll
    for (int mt = 0; mt < 4; mt++) {
        #pragma unroll
        for (int nt = 0; nt < 4; nt++) {
            int k = n0 + wn + nt * 8 + 2 * tig;
            float p0 = kpm[b * SS + k]     ? -1e30f : 0.0f;
            float p1 = kpm[b * SS + k + 1] ? -1e30f : 0.0f;
            #pragma unroll
            for (int half = 0; half < 2; half++) {
                int q = m0 + wm + mt * 16 + gid + half * 8;
                const float* am = attn_mask + (size_t)q * SS + k;
                float2 v = make_float2(acc[mt][nt][half * 2]     * 0.125f + am[0] + p0,
                                       acc[mt][nt][half * 2 + 1] * 0.125f + am[1] + p1);
                *(float2*)&pbase[(size_t)q * SS + k] = v;
            }
        }
    }
}

// ---------------- kernel 3: streaming softmax (in place) + attn_mean ----------------
__global__ void k_softmax(float* __restrict__ out_am) {
    int bq = blockIdx.x;
    int b = bq >> 11, q = bq & (SS - 1);
    int tid = threadIdx.x, wid = tid >> 5, lane = tid & 31;
    __shared__ float red[8];
    __shared__ float bc;
    float accv[8] = {};
    float* pbase = g_P + ((size_t)(b * HH) * SS + q) * SS;
    const size_t hstr = (size_t)SS * SS;
    const int c0 = tid * 8;

    for (int h = 0; h < HH; h++) {
        float* gr = pbase + h * hstr;
        float4 v0 = *(float4*)(gr + c0);
        float4 v1 = *(float4*)(gr + c0 + 4);
        float v[8] = {v0.x, v0.y, v0.z, v0.w, v1.x, v1.y, v1.z, v1.w};

        float mx = v[0];
        #pragma unroll
        for (int j = 1; j < 8; j++) mx = fmaxf(mx, v[j]);
        #pragma unroll
        for (int st = 16; st > 0; st >>= 1)
            mx = fmaxf(mx, __shfl_xor_sync(0xFFFFFFFF, mx, st));
        if (lane == 0) red[wid] = mx;
        __syncthreads();
        if (tid == 0) {
            float m = red[0];
            #pragma unroll
            for (int i = 1; i < 8; i++) m = fmaxf(m, red[i]);
            bc = m;
        }
        __syncthreads();
        mx = bc;

        float sum = 0.f;
        #pragma unroll
        for (int j = 0; j < 8; j++) { v[j] = __expf(v[j] - mx); sum += v[j]; }
        #pragma unroll
        for (int st = 16; st > 0; st >>= 1)
            sum += __shfl_xor_sync(0xFFFFFFFF, sum, st);
        __syncthreads();
        if (lane == 0) red[wid] = sum;
        __syncthreads();
        if (tid == 0) {
            float s = 0.f;
            #pragma unroll
            for (int i = 0; i < 8; i++) s += red[i];
            bc = s;
        }
        __syncthreads();
        float inv = 1.0f / bc;

        #pragma unroll
        for (int j = 0; j < 8; j++) { v[j] *= inv; accv[j] += v[j]; }
        *(float4*)(gr + c0)     = make_float4(v[0], v[1], v[2], v[3]);
        *(float4*)(gr + c0 + 4) = make_float4(v[4], v[5], v[6], v[7]);
        __syncthreads();
    }

    float* am = out_am + (size_t)bq * SS;
    *(float4*)(am + c0)     = make_float4(accv[0] * (1.0f / HH), accv[1] * (1.0f / HH),
                                          accv[2] * (1.0f / HH), accv[3] * (1.0f / HH));
    *(float4*)(am + c0 + 4) = make_float4(accv[4] * (1.0f / HH), accv[5] * (1.0f / HH),
                                          accv[6] * (1.0f / HH), accv[7] * (1.0f / HH));
}

// ---------------- kernel 4: O = P @ Vt^T ----------------
__global__ void k_pv() {
    constexpr int WN = 16;
    int bh = blockIdx.y, b = bh >> 4, h = bh & 15;
    int m0 = blockIdx.x * 128;
    const float* A  = g_P  + (size_t)bh * SS * SS;
    const float* Bv = g_Vt + (size_t)bh * DD * SS;   // [d][s] row-major = B[N][K]
    float acc[4][2][4] = {};
    gemm_mma<64>(A, SS, Bv, SS, m0, 0, SS, acc);
    EPI_SETUP();
    #pragma unroll
    for (int mt = 0; mt < 4; mt++) {
        #pragma unroll
        for (int nt = 0; nt < 2; nt++) {
            int dd = wn + nt * 8 + 2 * tig;
            #pragma unroll
            for (int half = 0; half < 2; half++) {
                int q = m0 + wm + mt * 16 + gid + half * 8;
                float2 v = make_float2(acc[mt][nt][half * 2], acc[mt][nt][half * 2 + 1]);
                *(float2*)&g_WA[(size_t)(b * SS + q) * EE + h * DD + dd] = v;
            }
        }
    }
}

// ---------------- kernel 5: out = WA @ out_w^T + out_b -> [S,B,E] ----------------
__global__ void k_out(const float* __restrict__ out_w, const float* __restrict__ out_b,
                      float* __restrict__ dout) {
    constexpr int WN = 32;
    int m0 = blockIdx.y * 128, n0 = blockIdx.x * 128;
    float acc[4][4][4] = {};
    gemm_mma<128>(g_WA, EE, out_w, EE, m0, n0, EE, acc);
    EPI_SETUP();
    #pragma unroll
    for (int mt = 0; mt < 4; mt++) {
        #pragma unroll
        for (int nt = 0; nt < 4; nt++) {
            int col = n0 + wn + nt * 8 + 2 * tig;
            float b0 = out_b[col], b1 = out_b[col + 1];
            #pragma unroll
            for (int half = 0; half < 2; half++) {
                int row = m0 + wm + mt * 16 + gid + half * 8;
                int b = row >> 11, s = row & (SS - 1);
                float2 v = make_float2(acc[mt][nt][half * 2] + b0,
                                       acc[mt][nt][half * 2 + 1] + b1);
                *(float2*)&dout[((size_t)s * BB + b) * EE + col] = v;
            }
        }
    }
}

// ---------------- launch ----------------
extern "C" void kernel_launch(void* const* d_in, const int* in_sizes, int n_in,
                              void* d_out, int out_size) {
    const float*         x         = (const float*)d_in[0];
    const float*         attn_mask = (const float*)d_in[1];
    const unsigned char* kpm       = (const unsigned char*)d_in[2];
    const float*         qkv_w     = (const float*)d_in[3];
    const float*         qkv_b     = (const float*)d_in[4];
    const float*         out_w     = (const float*)d_in[5];
    const float*         out_b     = (const float*)d_in[6];

    float* out    = (float*)d_out;
    float* out_am = out + (size_t)SS * BB * EE;

    const int smem128 = STG * (128 + 128) * PAD * 4;   // 61440
    const int smem64  = STG * (128 + 64)  * PAD * 4;   // 46080
    cudaFuncSetAttribute(k_qkv,    cudaFuncAttributeMaxDynamicSharedMemorySize, smem128);
    cudaFuncSetAttribute(k_scores, cudaFuncAttributeMaxDynamicSharedMemorySize, smem128);
    cudaFuncSetAttribute(k_out,    cudaFuncAttributeMaxDynamicSharedMemorySize, smem128);
    cudaFuncSetAttribute(k_pv,     cudaFuncAttributeMaxDynamicSharedMemorySize, smem64);

    k_qkv<<<dim3(3 * EE / 128, TOK / 128), NT, smem128>>>(x, qkv_w, qkv_b);
    k_scores<<<dim3(SS / 128, SS / 128, BH), NT, smem128>>>(attn_mask, kpm);
    k_softmax<<<BB * SS, 256>>>(out_am);
    k_pv<<<dim3(SS / 128, BH), NT, smem64>>>();
    k_out<<<dim3(EE / 128, TOK / 128), NT, smem128>>>(out_w, out_b, out);
}